// round 12
// baseline (speedup 1.0000x reference)
#include <cuda_runtime.h>
#include <math.h>
#include <stdint.h>

constexpr int B_ = 4, L_ = 2048, D_ = 256, P_ = 32;
constexpr int M_ = B_ * L_;
constexpr int CH_ = 64, NCH_ = L_ / CH_;
constexpr float PI_F = 3.14159265358979323846f;
constexpr float INV_SQRT_P = 0.17677669529663689f;   // 1/sqrt(32)

// ---------------- scratch ----------------
constexpr size_t O_POSC = 0;               // L*P
constexpr size_t O_POSS = 65536;
constexpr size_t O_POSW = 131072;
constexpr size_t O_V1   = 196608;          // M*P
constexpr size_t O_QC   = 458752;
constexpr size_t O_QS   = 720896;
constexpr size_t O_KC   = 983040;
constexpr size_t O_KS   = 1245184;
constexpr size_t O_CC   = 1507328;
constexpr size_t O_CS   = 1769472;
constexpr size_t O_M1R  = 2031616;
constexpr size_t O_GATE = 2293760;         // M
constexpr size_t O_GCUM = 2301952;         // M
constexpr size_t O_GV   = 2310144;         // M*D
constexpr size_t O_CTX  = 4407296;         // M*D
constexpr size_t O_H    = 6504448;         // M*D
constexpr size_t O_Y    = 8601600;         // M*D
constexpr size_t O_CTXS = 10698752;        // B*NCH*D
constexpr size_t O_A    = 10731520;        // B*NCH*2*P*D
constexpr size_t O_APRE = 12828672;        // B*NCH*2*P*D
constexpr size_t O_CTXS2 = 14925824;       // B*NCH*D
constexpr size_t BUF_SZ = 14958592;
__device__ __align__(256) float g_buf[BUF_SZ];

static __device__ __forceinline__ float wscan(float v, int lane) {
    #pragma unroll
    for (int o = 1; o < 32; o <<= 1) {
        float t = __shfl_up_sync(0xffffffffu, v, o);
        if (lane >= o) v += t;
    }
    return v;
}

static __device__ __forceinline__ float tf32r(float x) {
    uint32_t o;
    asm("cvt.rna.tf32.f32 %0, %1;" : "=r"(o) : "f"(x));
    return __uint_as_float(o);
}

static __device__ __forceinline__ void mma_tf32(float* c, float a0, float a1, float a2,
                                                float a3, float b0, float b1) {
    asm volatile(
        "mma.sync.aligned.m16n8k8.row.col.f32.tf32.tf32.f32 "
        "{%0,%1,%2,%3},{%4,%5,%6,%7},{%8,%9},{%0,%1,%2,%3};"
        : "+f"(c[0]), "+f"(c[1]), "+f"(c[2]), "+f"(c[3])
        : "r"(__float_as_uint(a0)), "r"(__float_as_uint(a1)),
          "r"(__float_as_uint(a2)), "r"(__float_as_uint(a3)),
          "r"(__float_as_uint(b0)), "r"(__float_as_uint(b1)));
}

// fragment-layout A-tile staging: value (row ar, k = kt8*8 + j) ->
// word offset (mt*2 + kt8)*128 + (r&7)*16 + (j&3)*4 + (r>>3) + 2*(j>>2)
// where mt = ar>>4, r = ar&15. A warp's fragment (mtile, ktile) is then one
// LDS.128 at (mtile*2+ktile)*128 + lane*4, with .x.y.z.w = a0..a3.
static __device__ __forceinline__ void store_afrag(float* as, int ar, int kt8,
                                                   float4 a0, float4 a1) {
    int base = ((ar >> 4) * 2 + kt8) * 128 + (ar & 7) * 16 + ((ar >> 3) & 1);
    as[base + 0]      = tf32r(a0.x);
    as[base + 4]      = tf32r(a0.y);
    as[base + 8]      = tf32r(a0.z);
    as[base + 12]     = tf32r(a0.w);
    as[base + 2]      = tf32r(a1.x);
    as[base + 6]      = tf32r(a1.y);
    as[base + 10]     = tf32r(a1.z);
    as[base + 14]     = tf32r(a1.w);
}

// pos_cos/pos_sin + posw = pos_phases @ w_off[D:,:] + b_off
__global__ void k_pos(const float* __restrict__ pp, const float* __restrict__ w_off,
                      const float* __restrict__ b_off, float* posc, float* poss, float* posw) {
    int idx = blockIdx.x * 256 + threadIdx.x;
    if (idx >= L_ * P_) return;
    int l = idx / P_, p = idx % P_;
    float ph = pp[idx];
    posc[idx] = cosf(ph);
    poss[idx] = sinf(ph);
    float acc = b_off[p];
    #pragma unroll 8
    for (int q = 0; q < P_; q++) acc += pp[l * P_ + q] * w_off[(D_ + q) * P_ + p];
    posw[idx] = acc;
}

// ---------------- P-wide projections on tensor cores (tf32 mma) ---------------
__launch_bounds__(256)
__global__ void k_pgemm(const float* __restrict__ A,
                        const float* __restrict__ w1v, const float* __restrict__ b1v,
                        const float* __restrict__ woff,
                        const float* __restrict__ wkey, const float* __restrict__ bkey,
                        const float* __restrict__ posw, const float* __restrict__ posc,
                        const float* __restrict__ poss,
                        float* v1, float* qc, float* qs, float* kc, float* ks,
                        int force_which) {
    __shared__ float As[2][2048];   // fragment layout: 8 mtiles x 2 ktiles x 128
    __shared__ float Ws[2][16 * 40];
    int tid = threadIdx.x, lane = tid & 31, warp = tid >> 5;
    int lr = lane >> 2, lc = lane & 3;
    int row0 = blockIdx.x * 128;
    int which = (force_which >= 0) ? force_which : (int)blockIdx.y;
    const float* W = (which == 0) ? w1v : (which == 1) ? woff : wkey;
    int warpM = warp * 16;

    float acc[4][4];
    #pragma unroll
    for (int j = 0; j < 4; j++)
        #pragma unroll
        for (int q = 0; q < 4; q++) acc[j][q] = 0.f;

    int ar = tid >> 1, akt = tid & 1, ak = akt * 8;
    int wr = tid >> 4, wc = (tid & 15) * 2;

    float4 a0, a1;
    float2 w2;
    a0 = *(const float4*)&A[(size_t)(row0 + ar) * 256 + ak];
    a1 = *(const float4*)&A[(size_t)(row0 + ar) * 256 + ak + 4];
    w2 = *(const float2*)&W[(size_t)wr * P_ + wc];
    store_afrag(As[0], ar, akt, a0, a1);
    Ws[0][wr * 40 + wc] = tf32r(w2.x);
    Ws[0][wr * 40 + wc + 1] = tf32r(w2.y);
    __syncthreads();

    for (int kt = 0; kt < 16; kt++) {
        int cur = kt & 1, nxt = cur ^ 1;
        if (kt + 1 < 16) {
            int gk = (kt + 1) * 16 + ak;
            a0 = *(const float4*)&A[(size_t)(row0 + ar) * 256 + gk];
            a1 = *(const float4*)&A[(size_t)(row0 + ar) * 256 + gk + 4];
            w2 = *(const float2*)&W[(size_t)((kt + 1) * 16 + wr) * P_ + wc];
        }
        #pragma unroll
        for (int kt8 = 0; kt8 < 2; kt8++) {
            int k0 = kt8 * 8;
            float4 af = *(const float4*)&As[cur][(warp * 2 + kt8) * 128 + lane * 4];
            #pragma unroll
            for (int j = 0; j < 4; j++) {
                float b0 = Ws[cur][(k0 + lc) * 40 + 8 * j + lr];
                float b1 = Ws[cur][(k0 + lc + 4) * 40 + 8 * j + lr];
                mma_tf32(acc[j], af.x, af.y, af.z, af.w, b0, b1);
            }
        }
        if (kt + 1 < 16) {
            store_afrag(As[nxt], ar, akt, a0, a1);
            Ws[nxt][wr * 40 + wc] = tf32r(w2.x);
            Ws[nxt][wr * 40 + wc + 1] = tf32r(w2.y);
        }
        __syncthreads();
    }

    #pragma unroll
    for (int h = 0; h < 2; h++) {
        int m = row0 + warpM + lr + 8 * h;
        int l = m & (L_ - 1);
        #pragma unroll
        for (int j = 0; j < 4; j++) {
            int n = 8 * j + 2 * lc;
            float c0 = acc[j][2 * h], c1 = acc[j][2 * h + 1];
            size_t oi = (size_t)m * P_ + n;
            if (which == 0) {
                float2 bb = *(const float2*)&b1v[n];
                float2 o; o.x = c0 + bb.x; o.y = c1 + bb.y;
                *(float2*)&v1[oi] = o;
            } else if (which == 1) {
                float ph0 = tanhf(c0 + posw[l * P_ + n]) * PI_F;
                float ph1 = tanhf(c1 + posw[l * P_ + n + 1]) * PI_F;
                float co0 = cosf(ph0), si0 = sinf(ph0);
                float co1 = cosf(ph1), si1 = sinf(ph1);
                float pc0 = posc[l * P_ + n], ps0 = poss[l * P_ + n];
                float pc1 = posc[l * P_ + n + 1], ps1 = poss[l * P_ + n + 1];
                float2 oc, os;
                oc.x = pc0 * co0 - ps0 * si0; oc.y = pc1 * co1 - ps1 * si1;
                os.x = ps0 * co0 + pc0 * si0; os.y = ps1 * co1 + pc1 * si1;
                *(float2*)&qc[oi] = oc;
                *(float2*)&qs[oi] = os;
            } else {
                float2 bb = *(const float2*)&bkey[n];
                float ph0 = tanhf(c0 + bb.x) * PI_F;
                float ph1 = tanhf(c1 + bb.y) * PI_F;
                float2 oc, os;
                oc.x = cosf(ph0); oc.y = cosf(ph1);
                os.x = sinf(ph0); os.y = sinf(ph1);
                *(float2*)&kc[oi] = oc;
                *(float2*)&ks[oi] = os;
            }
        }
    }
}

// ---------------- big GEMM on tensor cores (tf32 mma.sync) --------------------
enum { EPI_GATEMUL, EPI_GELU, EPI_RESID };
constexpr int WS_W = 72;

template <int K, int EPI, bool DUAL>
__launch_bounds__(256)
__global__ void k_bgemm(const float* __restrict__ A, const float* __restrict__ A2,
                        const float* __restrict__ W, const float* __restrict__ bias,
                        float* __restrict__ O1, const float* __restrict__ x1) {
    __shared__ float As[2][2048];   // fragment layout
    __shared__ float Ws[2][16 * WS_W];
    int tid = threadIdx.x;
    int lane = tid & 31, warp = tid >> 5;
    int warpM = (warp >> 1) * 32, warpN = (warp & 1) * 32;
    int mt0 = (warp >> 1) * 2;      // first mtile of this warp
    int lr = lane >> 2, lc = lane & 3;
    int row0 = blockIdx.x * 128, col0 = blockIdx.y * 64;

    float acc[2][4][4];
    #pragma unroll
    for (int i = 0; i < 2; i++)
        #pragma unroll
        for (int j = 0; j < 4; j++)
            #pragma unroll
            for (int q = 0; q < 4; q++) acc[i][j][q] = 0.f;

    int ar = tid >> 1, akt = tid & 1, ak = akt * 8;
    int wr = tid >> 4, wc = (tid & 15) * 4;
    constexpr int NT = K / 16;

    float4 a0, a1, w4;
    {
        const float* src;
        if constexpr (DUAL) src = &A[(size_t)(row0 + ar) * 256 + ak];
        else                src = &A[(size_t)(row0 + ar) * K + ak];
        a0 = *(const float4*)src;
        a1 = *(const float4*)(src + 4);
        w4 = *(const float4*)&W[(size_t)wr * D_ + col0 + wc];
    }
    store_afrag(As[0], ar, akt, a0, a1);
    {
        float* ws = &Ws[0][wr * WS_W + wc];
        ws[0] = tf32r(w4.x); ws[1] = tf32r(w4.y); ws[2] = tf32r(w4.z); ws[3] = tf32r(w4.w);
    }
    __syncthreads();

    for (int kt = 0; kt < NT; kt++) {
        int cur = kt & 1, nxt = cur ^ 1;
        if (kt + 1 < NT) {
            int gk = (kt + 1) * 16 + ak;
            const float* src;
            if constexpr (DUAL) src = (gk < 256) ? &A[(size_t)(row0 + ar) * 256 + gk]
                                                 : &A2[(size_t)(row0 + ar) * 256 + gk - 256];
            else                src = &A[(size_t)(row0 + ar) * K + gk];
            a0 = *(const float4*)src;
            a1 = *(const float4*)(src + 4);
            w4 = *(const float4*)&W[(size_t)((kt + 1) * 16 + wr) * D_ + col0 + wc];
        }
        #pragma unroll
        for (int kt8 = 0; kt8 < 2; kt8++) {
            int k0 = kt8 * 8;
            float4 af[2];
            #pragma unroll
            for (int i = 0; i < 2; i++)
                af[i] = *(const float4*)&As[cur][((mt0 + i) * 2 + kt8) * 128 + lane * 4];
            float bf[4][2];
            #pragma unroll
            for (int j = 0; j < 4; j++) {
                int bn = warpN + 8 * j + lr;
                bf[j][0] = Ws[cur][(k0 + lc) * WS_W + bn];
                bf[j][1] = Ws[cur][(k0 + lc + 4) * WS_W + bn];
            }
            #pragma unroll
            for (int i = 0; i < 2; i++)
                #pragma unroll
                for (int j = 0; j < 4; j++)
                    mma_tf32(acc[i][j], af[i].x, af[i].y, af[i].z, af[i].w,
                             bf[j][0], bf[j][1]);
        }
        if (kt + 1 < NT) {
            store_afrag(As[nxt], ar, akt, a0, a1);
            float* ws = &Ws[nxt][wr * WS_W + wc];
            ws[0] = tf32r(w4.x); ws[1] = tf32r(w4.y); ws[2] = tf32r(w4.z); ws[3] = tf32r(w4.w);
        }
        __syncthreads();
    }

    float2 bj[4];
    #pragma unroll
    for (int j = 0; j < 4; j++)
        bj[j] = *(const float2*)&bias[col0 + warpN + 8 * j + lc * 2];

    #pragma unroll
    for (int i = 0; i < 2; i++) {
        #pragma unroll
        for (int h = 0; h < 2; h++) {
            int m = row0 + warpM + 16 * i + lr + 8 * h;
            float g;
            if constexpr (EPI == EPI_GATEMUL) g = x1[m];
            #pragma unroll
            for (int j = 0; j < 4; j++) {
                int n = col0 + warpN + 8 * j + lc * 2;
                float v0 = acc[i][j][2 * h + 0] + bj[j].x;
                float v1 = acc[i][j][2 * h + 1] + bj[j].y;
                float2 o;
                if constexpr (EPI == EPI_GATEMUL) {
                    o.x = v0 * g;
                    o.y = v1 * g;
                } else if constexpr (EPI == EPI_GELU) {
                    o.x = 0.5f * v0 * (1.0f + erff(v0 * 0.70710678118654752f));
                    o.y = 0.5f * v1 * (1.0f + erff(v1 * 0.70710678118654752f));
                } else {
                    float2 xv = *(const float2*)&x1[(size_t)m * D_ + n];
                    o.x = xv.x + v0;
                    o.y = xv.y + v1;
                }
                *(float2*)&O1[(size_t)m * D_ + n] = o;
            }
        }
    }
}

// gate = sigmoid(x @ w_gate + b)
__global__ void k_gate(const float* __restrict__ x, const float* __restrict__ wg,
                       const float* __restrict__ bg, float* gate) {
    int w = threadIdx.x >> 5, lane = threadIdx.x & 31;
    int t = blockIdx.x * 8 + w;
    float acc = 0.f;
    #pragma unroll
    for (int i = 0; i < 8; i++) {
        int d = lane + i * 32;
        acc += x[(size_t)t * D_ + d] * wg[d];
    }
    #pragma unroll
    for (int o = 16; o > 0; o >>= 1) acc += __shfl_xor_sync(0xffffffffu, acc, o);
    if (lane == 0) gate[t] = 1.0f / (1.0f + expf(-(acc + bg[0])));
}

// parallel gate cumsum
__global__ void k_gscan(const float* __restrict__ gate, float* gcum) {
    __shared__ float wt[8];
    int b = blockIdx.x, tid = threadIdx.x, lane = tid & 31, warp = tid >> 5;
    int l0 = tid * 8;
    float v[8], t = 0.f;
    #pragma unroll
    for (int i = 0; i < 8; i++) { v[i] = gate[b * L_ + l0 + i]; t += v[i]; }
    float inc = wscan(t, lane);
    if (lane == 31) wt[warp] = inc;
    __syncthreads();
    float run = inc - t;
    for (int w = 0; w < warp; w++) run += wt[w];
    #pragma unroll
    for (int i = 0; i < 8; i++) {
        run += v[i];
        gcum[b * L_ + l0 + i] = fmaxf(1.0f, run);
    }
}

// context_avg 3-pass
__global__ void k_ctx1(const float* __restrict__ x, float* ctxs) {
    int b = blockIdx.x / NCH_, ch = blockIdx.x % NCH_, d = threadIdx.x;
    int m0 = b * L_ + ch * CH_;
    float acc = 0.f;
    #pragma unroll 8
    for (int l = 0; l < CH_; l++) acc += x[(size_t)(m0 + l) * D_ + d];
    ctxs[(b * NCH_ + ch) * D_ + d] = acc;
}
__global__ void k_ctx2(const float* __restrict__ ctxs, float* __restrict__ ctxs2) {
    int b = blockIdx.x, d = threadIdx.x;
    float v[NCH_];
    #pragma unroll
    for (int ch = 0; ch < NCH_; ch++) v[ch] = ctxs[(b * NCH_ + ch) * D_ + d];
    float run = 0.f;
    #pragma unroll
    for (int ch = 0; ch < NCH_; ch++) {
        ctxs2[(b * NCH_ + ch) * D_ + d] = run;
        run += v[ch];
    }
}
__global__ void k_ctx3(const float* __restrict__ x, const float* __restrict__ ctxs2, float* ctx) {
    int b = blockIdx.x / NCH_, ch = blockIdx.x % NCH_, d = threadIdx.x;
    float acc = ctxs2[(b * NCH_ + ch) * D_ + d];
    for (int l = 0; l < CH_; l++) {
        int gl = ch * CH_ + l;
        acc += x[(size_t)(b * L_ + gl) * D_ + d];
        ctx[(size_t)(b * L_ + gl) * D_ + d] = acc * (1.0f / (float)(gl + 1));
    }
}

// mem1 scan (parallel)
__global__ void k_m1scan(const float* __restrict__ v1, const float* __restrict__ posc,
                         const float* __restrict__ poss, const float* __restrict__ qc,
                         const float* __restrict__ qs, float* m1r) {
    __shared__ float wc_[8], ws_[8];
    int b = blockIdx.x / P_, p = blockIdx.x % P_;
    int tid = threadIdx.x, lane = tid & 31, warp = tid >> 5;
    int l0 = tid * 8;
    float c[8], s[8], tc = 0.f, ts = 0.f;
    #pragma unroll
    for (int i = 0; i < 8; i++) {
        int l = l0 + i;
        size_t m = (size_t)(b * L_ + l);
        float v = v1[m * P_ + p];
        c[i] = posc[l * P_ + p] * v;
        s[i] = poss[l * P_ + p] * v;
        tc += c[i];
        ts += s[i];
    }
    float ic = wscan(tc, lane), is_ = wscan(ts, lane);
    if (lane == 31) { wc_[warp] = ic; ws_[warp] = is_; }
    __syncthreads();
    float rc = ic - tc, rs = is_ - ts;
    for (int w = 0; w < warp; w++) { rc += wc_[w]; rs += ws_[w]; }
    #pragma unroll
    for (int i = 0; i < 8; i++) {
        rc += c[i];
        rs += s[i];
        size_t m = (size_t)(b * L_ + l0 + i);
        m1r[m * P_ + p] = (rc * qc[m * P_ + p] + rs * qs[m * P_ + p]) * INV_SQRT_P;
    }
}

// ---------------- kv pass1 on tensor cores, 3xTF32 (fp32-grade accuracy) ------
constexpr int KV1_SMEM = (2 * 64 * 72 + 2 * 16 * 264) * 4;  // 70656 B

__launch_bounds__(256)
__global__ void k_kv1(const float* __restrict__ cc, const float* __restrict__ cs,
                      const float* __restrict__ gv, float* __restrict__ A) {
    extern __shared__ float sm[];
    float* sCH = sm;                 // 64 x 72  (cc|cs hi, [l][row])
    float* sCL = sm + 4608;          // lo
    float* sGH = sm + 9216;          // 16 x 264 (gv stage hi, [l][d])
    float* sGL = sm + 9216 + 4224;   // lo
    int b = blockIdx.x / NCH_, ch = blockIdx.x % NCH_;
    int m0 = b * L_ + ch * CH_;
    int tid = threadIdx.x, lane = tid & 31, warp = tid >> 5;
    int lr = lane >> 2, lc = lane & 3;
    int wm = (warp >> 2) * 32, wn = (warp & 3) * 64;

    for (int i = tid; i < 64 * 64; i += 256) {
        int l = i >> 6, row = i & 63;
        float v = (row < 32) ? cc[(size_t)(m0 + l) * P_ + row]
                             : cs[(size_t)(m0 + l) * P_ + row - 32];
        float hi = tf32r(v);
        sCH[l * 72 + row] = hi;
        sCL[l * 72 + row] = tf32r(v - hi);
    }

    float acc[2][8][4];
    #pragma unroll
    for (int i = 0; i < 2; i++)
        #pragma unroll
        for (int j = 0; j < 8; j++)
            #pragma unroll
            for (int q = 0; q < 4; q++) acc[i][j][q] = 0.f;

    int r = tid >> 4, c0 = (tid & 15) * 16;
    for (int st = 0; st < 4; st++) {
        #pragma unroll
        for (int q = 0; q < 4; q++) {
            float4 v4 = *(const float4*)&gv[(size_t)(m0 + st * 16 + r) * D_ + c0 + q * 4];
            float h0 = tf32r(v4.x), h1 = tf32r(v4.y), h2 = tf32r(v4.z), h3 = tf32r(v4.w);
            float* gh = &sGH[r * 264 + c0 + q * 4];
            float* gl = &sGL[r * 264 + c0 + q * 4];
            gh[0] = h0; gh[1] = h1; gh[2] = h2; gh[3] = h3;
            gl[0] = tf32r(v4.x - h0); gl[1] = tf32r(v4.y - h1);
            gl[2] = tf32r(v4.z - h2); gl[3] = tf32r(v4.w - h3);
        }
        __syncthreads();
        #pragma unroll
        for (int k0 = 0; k0 < 16; k0 += 8) {
            int kk = st * 16 + k0;
            float ah[2][4], al[2][4];
            #pragma unroll
            for (int i = 0; i < 2; i++) {
                int row = wm + 16 * i + lr;
                ah[i][0] = sCH[(kk + lc) * 72 + row];
                ah[i][1] = sCH[(kk + lc) * 72 + row + 8];
                ah[i][2] = sCH[(kk + lc + 4) * 72 + row];
                ah[i][3] = sCH[(kk + lc + 4) * 72 + row + 8];
                al[i][0] = sCL[(kk + lc) * 72 + row];
                al[i][1] = sCL[(kk + lc) * 72 + row + 8];
                al[i][2] = sCL[(kk + lc + 4) * 72 + row];
                al[i][3] = sCL[(kk + lc + 4) * 72 + row + 8];
            }
            #pragma unroll
            for (int j = 0; j < 8; j++) {
                int nn = wn + 8 * j + lr;
                float bh0 = sGH[(k0 + lc) * 264 + nn];
                float bh1 = sGH[(k0 + lc + 4) * 264 + nn];
                float bl0 = sGL[(k0 + lc) * 264 + nn];
                float bl1 = sGL[(k0 + lc + 4) * 264 + nn];
                #pragma unroll
                for (int i = 0; i < 2; i++) {
                    mma_tf32(acc[i][j], ah[i][0], ah[i][1], ah[i][2], ah[i][3], bh0, bh1);
                    mma_tf32(acc[i][j], ah[i][0], ah[i][1], ah[i][2], ah[i][3], bl0, bl1);
                    mma_tf32(acc[i][j], al[i][0], al[i][1], al[i][2], al[i][3], bh0, bh1);
                }
            }
        }
        __syncthreads();
    }

    size_t base = (size_t)(b * NCH_ + ch) * 2 * P_ * D_;
    #pragma unroll
    for (int i = 0; i < 2; i++)
        #pragma unroll
        for (int h = 0; h < 2; h++) {
            int row = wm + 16 * i + lr + 8 * h;
            #pragma unroll
            for (int j = 0; j < 8; j++) {
                int col = wn + 8 * j + 2 * lc;
                float2 o;
                o.x = acc[i][j][2 * h + 0];
                o.y = acc[i][j][2 * h + 1];
                *(float2*)&A[base + (size_t)row * D_ + col] = o;
            }
        }
}

// kv pass2: exclusive prefix of A over chunks (batched loads)
__global__ void k_kv2(const float* __restrict__ A, float* __restrict__ Apre) {
    int idx = blockIdx.x * 256 + threadIdx.x;
    int e = idx % (2 * P_ * D_), b = idx / (2 * P_ * D_);
    float v[NCH_];
    #pragma unroll
    for (int ch = 0; ch < NCH_; ch++)
        v[ch] = A[(size_t)(b * NCH_ + ch) * 2 * P_ * D_ + e];
    float run = 0.f;
    #pragma unroll
    for (int ch = 0; ch < NCH_; ch++) {
        Apre[(size_t)(b * NCH_ + ch) * 2 * P_ * D_ + e] = run;
        run += v[ch];
    }
}

// ---------------- kv pass3: fully tensorized + fused LN ----------------
constexpr int SK_  = 0;        // 64 x 68  (kc|ks tf32)
constexpr int SC_  = 4352;     // 64 x 68  (cc|cs tf32)
constexpr int SAC_ = 8704;     // 64 x 164 (A operand: scores|K2|m1r)
constexpr int SBT_ = 0;        // 16 x 260 (B staging, reuses SK after phase1)
constexpr int SOUT_ = 0;       // 64 x 260 (result, reuses all after phase2)
constexpr int KV3_SMEM = 19200 * 4;   // 76800 bytes

__launch_bounds__(256)
__global__ void k_kv3(const float* __restrict__ kc, const float* __restrict__ ks,
                      const float* __restrict__ cc, const float* __restrict__ cs,
                      const float* __restrict__ gv, const float* __restrict__ Apre,
                      const float* __restrict__ m1r, const float* __restrict__ gcum,
                      const float* __restrict__ w_mo, const float* __restrict__ b_mo,
                      const float* __restrict__ lng, const float* __restrict__ lnb,
                      float* __restrict__ y) {
    extern __shared__ float sm[];
    __shared__ float s_scl[64];
    int b = blockIdx.x / NCH_, ch = blockIdx.x % NCH_;
    int m0 = b * L_ + ch * CH_;
    int tid = threadIdx.x, lane = tid & 31, warp = tid >> 5;
    int lr = lane >> 2, lc = lane & 3;

    for (int i = tid; i < CH_ * P_; i += 256) {
        int l = i >> 5, p = i & 31;
        size_t gi = (size_t)(m0 + l) * P_ + p;
        sm[SK_ + l * 68 + p]      = tf32r(kc[gi]);
        sm[SK_ + l * 68 + 32 + p] = tf32r(ks[gi]);
        sm[SC_ + l * 68 + p]      = tf32r(cc[gi]);
        sm[SC_ + l * 68 + 32 + p] = tf32r(cs[gi]);
        sm[SAC_ + l * 164 + 128 + p] = tf32r(m1r[gi]);
    }
    if (tid < 64) s_scl[tid] = rsqrtf(gcum[m0 + tid]) * INV_SQRT_P;
    __syncthreads();

    // phase 1: scores[64,64] = [kc|ks] @ [cc|cs]^T (K=64), warps 2x4 (32x16)
    {
        int wm = (warp >> 2) * 32, wn = (warp & 3) * 16;
        float a2[2][2][4];
        #pragma unroll
        for (int i = 0; i < 2; i++)
            #pragma unroll
            for (int j = 0; j < 2; j++)
                #pragma unroll
                for (int q = 0; q < 4; q++) a2[i][j][q] = 0.f;
        #pragma unroll
        for (int kk = 0; kk < 8; kk++) {
            int k0 = kk * 8;
            float af[2][4];
            #pragma unroll
            for (int i = 0; i < 2; i++) {
                int row = wm + 16 * i + lr;
                af[i][0] = sm[SK_ + row * 68 + k0 + lc];
                af[i][1] = sm[SK_ + (row + 8) * 68 + k0 + lc];
                af[i][2] = sm[SK_ + row * 68 + k0 + lc + 4];
                af[i][3] = sm[SK_ + (row + 8) * 68 + k0 + lc + 4];
            }
            #pragma unroll
            for (int j = 0; j < 2; j++) {
                int nn = wn + 8 * j + lr;
                float b0 = sm[SC_ + nn * 68 + k0 + lc];
                float b1 = sm[SC_ + nn * 68 + k0 + lc + 4];
                #pragma unroll
                for (int i = 0; i < 2; i++)
                    mma_tf32(a2[i][j], af[i][0], af[i][1], af[i][2], af[i][3], b0, b1);
            }
        }
        #pragma unroll
        for (int i = 0; i < 2; i++)
            #pragma unroll
            for (int j = 0; j < 2; j++)
                #pragma unroll
                for (int h = 0; h < 2; h++) {
                    int row = wm + 16 * i + lr + 8 * h;
                    float sl = s_scl[row];
                    int col = wn + 8 * j + 2 * lc;
                    sm[SAC_ + row * 164 + col] =
                        (col <= row) ? tf32r(a2[i][j][2 * h] * sl) : 0.f;
                    sm[SAC_ + row * 164 + col + 1] =
                        (col + 1 <= row) ? tf32r(a2[i][j][2 * h + 1] * sl) : 0.f;
                }
    }
    // K2 columns: s_ac[l][64+c] = scl[l] * [kc|ks][l][c]
    #pragma unroll
    for (int t = 0; t < 16; t++) {
        int idx = tid * 16 + t;
        int l = idx >> 6, c = idx & 63;
        sm[SAC_ + l * 164 + 64 + c] = tf32r(s_scl[l] * sm[SK_ + l * 68 + c]);
    }
    __syncthreads();

    // phase 2: [64,160] @ [160,256], warps 2x4 (32x64)
    float acc[2][8][4];
    #pragma unroll
    for (int i = 0; i < 2; i++)
        #pragma unroll
        for (int j = 0; j < 8; j++)
            #pragma unroll
            for (int q = 0; q < 4; q++) acc[i][j][q] = 0.f;
    int wm2 = (warp >> 2) * 32, wn2 = (warp & 3) * 64;
    size_t abase = (size_t)(b * NCH_ + ch) * 2 * P_ * D_;
    for (int st = 0; st < 10; st++) {
        int r = tid >> 4, c0 = (tid & 15) * 16;
        int gr = st * 16 + r;
        const float* src;
        if (gr < 64)       src = &gv[(size_t)(m0 + gr) * D_];
        else if (gr < 128) src = &Apre[abase + (size_t)(gr - 64) * D_];
        else               src = &w_mo[(size_t)(gr - 128) * D_];
        #pragma unroll
        for (int q = 0; q < 4; q++) {
            float4 v = *(const float4*)&src[c0 + q * 4];
            float* dst = &sm[SBT_ + r * 260 + c0 + q * 4];
            dst[0] = tf32r(v.x); dst[1] = tf32r(v.y);
            dst[2] = tf32r(v.z); dst[3] = tf32r(v.w);
        }
        __syncthreads();
        #pragma unroll
        for (int k0 = 0; k0 < 16; k0 += 8) {
            float af[2][4];
            #pragma unroll
            for (int i = 0; i < 2; i++) {
                int row = wm2 + 16 * i + lr;
                af[i][0] = sm[SAC_ + row * 164 + st * 16 + k0 + lc];
                af[i][1] = sm[SAC_ + (row + 8) * 164 + st * 16 + k0 + lc];
                af[i][2] = sm[SAC_ + row * 164 + st * 16 + k0 + lc + 4];
                af[i][3] = sm[SAC_ + (row + 8) * 164 + st * 16 + k0 + lc + 4];
            }
            #pragma unroll
            for (int j = 0; j < 8; j++) {
                int nn = wn2 + 8 * j + lr;
                float b0 = sm[SBT_ + (k0 + lc) * 260 + nn];
                float b1 = sm[SBT_ + (k0 + lc + 4) * 260 + nn];
                #pragma unroll
                for (int i = 0; i < 2; i++)
                    mma_tf32(acc[i][j], af[i][0], af[i][1], af[i][2], af[i][3], b0, b1);
            }
        }
        __syncthreads();
    }

    // stash result (+bias) in smem for the LN pass
    #pragma unroll
    for (int j = 0; j < 8; j++) {
        int col = wn2 + 8 * j + 2 * lc;
        float2 bb = *(const float2*)&b_mo[col];
        #pragma unroll
        for (int i = 0; i < 2; i++) {
            int row = wm2 + 16 * i + lr;
            sm[SOUT_ + row * 260 + col]           = acc[i][j][0] + bb.x;
            sm[SOUT_ + row * 260 + col + 1]       = acc[i][j][1] + bb.y;
            sm[SOUT_ + (row + 8) * 260 + col]     = acc[i][j][2] + bb.x;
            sm[SOUT_ + (row + 8) * 260 + col + 1] = acc[i][j][3] + bb.y;
        }
    }
    __syncthreads();

    // LayerNorm: warp w handles rows w*8 .. w*8+7
    for (int rr = 0; rr < 8; rr++) {
        int r = warp * 8 + rr;
        float v[8], s = 0.f;
        #pragma unroll
        for (int q = 0; q < 8; q++) {
            v[q] = sm[SOUT_ + r * 260 + lane + 32 * q];
            s += v[q];
        }
        #pragma unroll
        for (int o = 16; o > 0; o >>= 1) s += __shfl_xor_sync(0xffffffffu, s, o);
        float mu = s * (1.0f / 256.0f);
        float qv = 0.f;
        #pragma unroll
        for (int q = 0; q < 8; q++) { float d = v[q] - mu; qv += d * d; }
        #pragma unroll
        for (int o = 16; o > 0; o >>= 1) qv += __shfl_xor_sync(0xffffffffu, qv, o);
        float inv = rsqrtf(qv * (1.0f / 256.0f) + 1e-5f);
        int m = m0 + r;
        #pragma unroll
        for (int q = 0; q < 8; q++) {
            int n = lane + 32 * q;
            y[(size_t)m * D_ + n] = (v[q] - mu) * inv * lng[n] + lnb[n];
        }
    }
}

extern "C" void kernel_launch(void* const* d_in, const int* in_sizes, int n_in,
                              void* d_out, int out_size) {
    const float* x       = (const float*)d_in[0];
    const float* pp      = (const float*)d_in[1];
    const float* w_mem1v = (const float*)d_in[2];
    const float* b_mem1v = (const float*)d_in[3];
    const float* w_mem1o = (const float*)d_in[4];
    const float* b_mem1o = (const float*)d_in[5];
    const float* w_off   = (const float*)d_in[6];
    const float* b_off   = (const float*)d_in[7];
    const float* w_key   = (const float*)d_in[8];
    const float* b_key   = (const float*)d_in[9];
    const float* w_val   = (const float*)d_in[10];
    const float* b_val   = (const float*)d_in[11];
    const float* w_sk1   = (const float*)d_in[12];
    const float* b_sk1   = (const float*)d_in[13];
    const float* w_sk2   = (const float*)d_in[14];
    const float* b_sk2   = (const float*)d_in[15];
    const float* w_gate  = (const float*)d_in[16];
    const float* b_gate  = (const float*)d_in[17];
    const float* ln_g    = (const float*)d_in[18];
    const float* ln_b    = (const float*)d_in[19];
    const float* w_out   = (const float*)d_in[20];
    const float* b_out   = (const float*)d_in[21];
    float* out = (float*)d_out;

    float* base = nullptr;
    cudaGetSymbolAddress((void**)&base, g_buf);
    float* posc = base + O_POSC; float* poss = base + O_POSS; float* posw = base + O_POSW;
    float* v1   = base + O_V1;   float* qc   = base + O_QC;   float* qs   = base + O_QS;
    float* kc   = base + O_KC;   float* ks   = base + O_KS;   float* ccp  = base + O_CC;
    float* csp  = base + O_CS;   float* m1r  = base + O_M1R;  float* gate = base + O_GATE;
    float* gcum = base + O_GCUM; float* gv   = base + O_GV;   float* ctx  = base + O_CTX;
    float* h    = base + O_H;    float* y    = base + O_Y;
    float* ctxs = base + O_CTXS; float* Am   = base + O_A;    float* Apre = base + O_APRE;
    float* ctxs2 = base + O_CTXS2;

    cudaFuncSetAttribute(k_kv3, cudaFuncAttributeMaxDynamicSharedMemorySize, KV3_SMEM);
    cudaFuncSetAttribute(k_kv1, cudaFuncAttributeMaxDynamicSharedMemorySize, KV1_SMEM);

    dim3 gP(M_ / 128, 3);
    dim3 gBig(M_ / 128, 4);

    // order chosen so the profiled launch (index 3) is the big sk1 GEMM
    k_ctx1<<<B_ * NCH_, 256>>>(x, ctxs);
    k_ctx2<<<B_, 256>>>(ctxs, ctxs2);
    k_ctx3<<<B_ * NCH_, 256>>>(x, ctxs2, ctx);
    k_bgemm<512, EPI_GELU, true><<<gBig, 256>>>(x, ctx, w_sk1, b_sk1, h, nullptr);
    k_pos<<<(L_ * P_ + 255) / 256, 256>>>(pp, w_off, b_off, posc, poss, posw);
    k_pgemm<<<gP, 256>>>(x, w_mem1v, b_mem1v, w_off, w_key, b_key, posw, posc, poss,
                         v1, qc, qs, kc, ks, -1);
    k_gate<<<M_ / 8, 256>>>(x, w_gate, b_gate, gate);
    k_gscan<<<B_, 256>>>(gate, gcum);
    k_bgemm<256, EPI_GATEMUL, false><<<gBig, 256>>>(x, nullptr, w_val, b_val, gv, gate);
    k_pgemm<<<dim3(M_ / 128, 1), 256>>>(h, nullptr, nullptr, nullptr, w_sk2, b_sk2,
                                        nullptr, nullptr, nullptr,
                                        nullptr, nullptr, nullptr, ccp, csp, 2);
    k_m1scan<<<B_ * P_, 256>>>(v1, posc, poss, qc, qs, m1r);
    k_kv1<<<B_ * NCH_, 256, KV1_SMEM>>>(ccp, csp, gv, Am);
    k_kv2<<<B_ * 2 * P_ * D_ / 256, 256>>>(Am, Apre);
    k_kv3<<<B_ * NCH_, 256, KV3_SMEM>>>(kc, ks, ccp, csp, gv, Apre, m1r, gcum,
                                        w_mem1o, b_mem1o, ln_g, ln_b, y);
    k_bgemm<256, EPI_RESID, false><<<gBig, 256>>>(y, nullptr, w_out, b_out, out, x);
}

// round 13
// speedup vs baseline: 1.1816x; 1.1816x over previous
#include <cuda_runtime.h>
#include <math.h>
#include <stdint.h>

constexpr int B_ = 4, L_ = 2048, D_ = 256, P_ = 32;
constexpr int M_ = B_ * L_;
constexpr int CH_ = 64, NCH_ = L_ / CH_;
constexpr float PI_F = 3.14159265358979323846f;
constexpr float INV_SQRT_P = 0.17677669529663689f;   // 1/sqrt(32)

// ---------------- scratch ----------------
constexpr size_t O_POSC = 0;               // L*P
constexpr size_t O_POSS = 65536;
constexpr size_t O_POSW = 131072;
constexpr size_t O_V1   = 196608;          // M*P
constexpr size_t O_QC   = 458752;
constexpr size_t O_QS   = 720896;
constexpr size_t O_KC   = 983040;
constexpr size_t O_KS   = 1245184;
constexpr size_t O_CC   = 1507328;
constexpr size_t O_CS   = 1769472;
constexpr size_t O_M1R  = 2031616;
constexpr size_t O_GATE = 2293760;         // M
constexpr size_t O_GCUM = 2301952;         // M
constexpr size_t O_GV   = 2310144;         // M*D
constexpr size_t O_CTX  = 4407296;         // M*D
constexpr size_t O_H    = 6504448;         // M*D
constexpr size_t O_Y    = 8601600;         // M*D
constexpr size_t O_CTXS = 10698752;        // B*NCH*D
constexpr size_t O_A    = 10731520;        // B*NCH*2*P*D
constexpr size_t O_APRE = 12828672;        // B*NCH*2*P*D
constexpr size_t O_CTXS2 = 14925824;       // B*NCH*D
constexpr size_t BUF_SZ = 14958592;
__device__ __align__(256) float g_buf[BUF_SZ];

static __device__ __forceinline__ float wscan(float v, int lane) {
    #pragma unroll
    for (int o = 1; o < 32; o <<= 1) {
        float t = __shfl_up_sync(0xffffffffu, v, o);
        if (lane >= o) v += t;
    }
    return v;
}

static __device__ __forceinline__ float tf32r(float x) {
    uint32_t o;
    asm("cvt.rna.tf32.f32 %0, %1;" : "=r"(o) : "f"(x));
    return __uint_as_float(o);
}

static __device__ __forceinline__ void mma_tf32(float* c, float a0, float a1, float a2,
                                                float a3, float b0, float b1) {
    asm volatile(
        "mma.sync.aligned.m16n8k8.row.col.f32.tf32.tf32.f32 "
        "{%0,%1,%2,%3},{%4,%5,%6,%7},{%8,%9},{%0,%1,%2,%3};"
        : "+f"(c[0]), "+f"(c[1]), "+f"(c[2]), "+f"(c[3])
        : "r"(__float_as_uint(a0)), "r"(__float_as_uint(a1)),
          "r"(__float_as_uint(a2)), "r"(__float_as_uint(a3)),
          "r"(__float_as_uint(b0)), "r"(__float_as_uint(b1)));
}

// Pair-permuted A staging. k-group of 8 stored as pairs (k, k+4):
//   off(kt8, row, k) = kt8*1028 + row*8 + (k&3)*2 + (k>>2)
// Store: 2x STS.128 per thread, conflict-free (granule kt8*257+ar*2 distinct per phase).
// Read: LDS.64 at row*8 + 2*lc gives (a[k=lc], a[k=lc+4]); banks lr*8+2lc distinct per phase.
constexpr int AKT_STRIDE = 1028;
constexpr int A_TILE_WORDS = 2 * AKT_STRIDE;   // 2056

static __device__ __forceinline__ void store_afrag(float* as, int ar, int kt8,
                                                   float4 a0, float4 a1) {
    float* p = &as[kt8 * AKT_STRIDE + ar * 8];
    float4 v1 = make_float4(tf32r(a0.x), tf32r(a1.x), tf32r(a0.y), tf32r(a1.y));
    float4 v2 = make_float4(tf32r(a0.z), tf32r(a1.z), tf32r(a0.w), tf32r(a1.w));
    *(float4*)p = v1;
    *(float4*)(p + 4) = v2;
}

// pos_cos/pos_sin + posw = pos_phases @ w_off[D:,:] + b_off
__global__ void k_pos(const float* __restrict__ pp, const float* __restrict__ w_off,
                      const float* __restrict__ b_off, float* posc, float* poss, float* posw) {
    int idx = blockIdx.x * 256 + threadIdx.x;
    if (idx >= L_ * P_) return;
    int l = idx / P_, p = idx % P_;
    float ph = pp[idx];
    posc[idx] = cosf(ph);
    poss[idx] = sinf(ph);
    float acc = b_off[p];
    #pragma unroll 8
    for (int q = 0; q < P_; q++) acc += pp[l * P_ + q] * w_off[(D_ + q) * P_ + p];
    posw[idx] = acc;
}

// ---------------- P-wide projections on tensor cores (tf32 mma) ---------------
__launch_bounds__(256)
__global__ void k_pgemm(const float* __restrict__ A,
                        const float* __restrict__ w1v, const float* __restrict__ b1v,
                        const float* __restrict__ woff,
                        const float* __restrict__ wkey, const float* __restrict__ bkey,
                        const float* __restrict__ posw, const float* __restrict__ posc,
                        const float* __restrict__ poss,
                        float* v1, float* qc, float* qs, float* kc, float* ks,
                        int force_which) {
    __shared__ float As[2][A_TILE_WORDS];
    __shared__ float Ws[2][16 * 40];
    int tid = threadIdx.x, lane = tid & 31, warp = tid >> 5;
    int lr = lane >> 2, lc = lane & 3;
    int row0 = blockIdx.x * 128;
    int which = (force_which >= 0) ? force_which : (int)blockIdx.y;
    const float* W = (which == 0) ? w1v : (which == 1) ? woff : wkey;
    int warpM = warp * 16;

    float acc[4][4];
    #pragma unroll
    for (int j = 0; j < 4; j++)
        #pragma unroll
        for (int q = 0; q < 4; q++) acc[j][q] = 0.f;

    int ar = tid >> 1, akt = tid & 1, ak = akt * 8;
    int wr = tid >> 4, wc = (tid & 15) * 2;

    float4 a0, a1;
    float2 w2;
    a0 = *(const float4*)&A[(size_t)(row0 + ar) * 256 + ak];
    a1 = *(const float4*)&A[(size_t)(row0 + ar) * 256 + ak + 4];
    w2 = *(const float2*)&W[(size_t)wr * P_ + wc];
    store_afrag(As[0], ar, akt, a0, a1);
    Ws[0][wr * 40 + wc] = tf32r(w2.x);
    Ws[0][wr * 40 + wc + 1] = tf32r(w2.y);
    __syncthreads();

    for (int kt = 0; kt < 16; kt++) {
        int cur = kt & 1, nxt = cur ^ 1;
        if (kt + 1 < 16) {
            int gk = (kt + 1) * 16 + ak;
            a0 = *(const float4*)&A[(size_t)(row0 + ar) * 256 + gk];
            a1 = *(const float4*)&A[(size_t)(row0 + ar) * 256 + gk + 4];
            w2 = *(const float2*)&W[(size_t)((kt + 1) * 16 + wr) * P_ + wc];
        }
        #pragma unroll
        for (int kt8 = 0; kt8 < 2; kt8++) {
            int k0 = kt8 * 8;
            float2 p1 = *(const float2*)&As[cur][kt8 * AKT_STRIDE + (warpM + lr) * 8 + 2 * lc];
            float2 p2 = *(const float2*)&As[cur][kt8 * AKT_STRIDE + (warpM + lr + 8) * 8 + 2 * lc];
            #pragma unroll
            for (int j = 0; j < 4; j++) {
                float b0 = Ws[cur][(k0 + lc) * 40 + 8 * j + lr];
                float b1 = Ws[cur][(k0 + lc + 4) * 40 + 8 * j + lr];
                mma_tf32(acc[j], p1.x, p2.x, p1.y, p2.y, b0, b1);
            }
        }
        if (kt + 1 < 16) {
            store_afrag(As[nxt], ar, akt, a0, a1);
            Ws[nxt][wr * 40 + wc] = tf32r(w2.x);
            Ws[nxt][wr * 40 + wc + 1] = tf32r(w2.y);
        }
        __syncthreads();
    }

    #pragma unroll
    for (int h = 0; h < 2; h++) {
        int m = row0 + warpM + lr + 8 * h;
        int l = m & (L_ - 1);
        #pragma unroll
        for (int j = 0; j < 4; j++) {
            int n = 8 * j + 2 * lc;
            float c0 = acc[j][2 * h], c1 = acc[j][2 * h + 1];
            size_t oi = (size_t)m * P_ + n;
            if (which == 0) {
                float2 bb = *(const float2*)&b1v[n];
                float2 o; o.x = c0 + bb.x; o.y = c1 + bb.y;
                *(float2*)&v1[oi] = o;
            } else if (which == 1) {
                float ph0 = tanhf(c0 + posw[l * P_ + n]) * PI_F;
                float ph1 = tanhf(c1 + posw[l * P_ + n + 1]) * PI_F;
                float co0 = cosf(ph0), si0 = sinf(ph0);
                float co1 = cosf(ph1), si1 = sinf(ph1);
                float pc0 = posc[l * P_ + n], ps0 = poss[l * P_ + n];
                float pc1 = posc[l * P_ + n + 1], ps1 = poss[l * P_ + n + 1];
                float2 oc, os;
                oc.x = pc0 * co0 - ps0 * si0; oc.y = pc1 * co1 - ps1 * si1;
                os.x = ps0 * co0 + pc0 * si0; os.y = ps1 * co1 + pc1 * si1;
                *(float2*)&qc[oi] = oc;
                *(float2*)&qs[oi] = os;
            } else {
                float2 bb = *(const float2*)&bkey[n];
                float ph0 = tanhf(c0 + bb.x) * PI_F;
                float ph1 = tanhf(c1 + bb.y) * PI_F;
                float2 oc, os;
                oc.x = cosf(ph0); oc.y = cosf(ph1);
                os.x = sinf(ph0); os.y = sinf(ph1);
                *(float2*)&kc[oi] = oc;
                *(float2*)&ks[oi] = os;
            }
        }
    }
}

// ---------------- big GEMM on tensor cores (tf32 mma.sync) --------------------
enum { EPI_GATEMUL, EPI_GELU, EPI_RESID };
constexpr int WS_W = 72;

template <int K, int EPI, bool DUAL>
__launch_bounds__(256)
__global__ void k_bgemm(const float* __restrict__ A, const float* __restrict__ A2,
                        const float* __restrict__ W, const float* __restrict__ bias,
                        float* __restrict__ O1, const float* __restrict__ x1) {
    __shared__ float As[2][A_TILE_WORDS];
    __shared__ float Ws[2][16 * WS_W];
    int tid = threadIdx.x;
    int lane = tid & 31, warp = tid >> 5;
    int warpM = (warp >> 1) * 32, warpN = (warp & 1) * 32;
    int lr = lane >> 2, lc = lane & 3;
    int row0 = blockIdx.x * 128, col0 = blockIdx.y * 64;

    float acc[2][4][4];
    #pragma unroll
    for (int i = 0; i < 2; i++)
        #pragma unroll
        for (int j = 0; j < 4; j++)
            #pragma unroll
            for (int q = 0; q < 4; q++) acc[i][j][q] = 0.f;

    int ar = tid >> 1, akt = tid & 1, ak = akt * 8;
    int wr = tid >> 4, wc = (tid & 15) * 4;
    constexpr int NT = K / 16;

    float4 a0, a1, w4;
    {
        const float* src;
        if constexpr (DUAL) src = &A[(size_t)(row0 + ar) * 256 + ak];
        else                src = &A[(size_t)(row0 + ar) * K + ak];
        a0 = *(const float4*)src;
        a1 = *(const float4*)(src + 4);
        w4 = *(const float4*)&W[(size_t)wr * D_ + col0 + wc];
    }
    store_afrag(As[0], ar, akt, a0, a1);
    {
        float* ws = &Ws[0][wr * WS_W + wc];
        ws[0] = tf32r(w4.x); ws[1] = tf32r(w4.y); ws[2] = tf32r(w4.z); ws[3] = tf32r(w4.w);
    }
    __syncthreads();

    for (int kt = 0; kt < NT; kt++) {
        int cur = kt & 1, nxt = cur ^ 1;
        if (kt + 1 < NT) {
            int gk = (kt + 1) * 16 + ak;
            const float* src;
            if constexpr (DUAL) src = (gk < 256) ? &A[(size_t)(row0 + ar) * 256 + gk]
                                                 : &A2[(size_t)(row0 + ar) * 256 + gk - 256];
            else                src = &A[(size_t)(row0 + ar) * K + gk];
            a0 = *(const float4*)src;
            a1 = *(const float4*)(src + 4);
            w4 = *(const float4*)&W[(size_t)((kt + 1) * 16 + wr) * D_ + col0 + wc];
        }
        #pragma unroll
        for (int kt8 = 0; kt8 < 2; kt8++) {
            int k0 = kt8 * 8;
            float2 p1[2], p2[2];
            #pragma unroll
            for (int i = 0; i < 2; i++) {
                int arow = warpM + 16 * i + lr;
                p1[i] = *(const float2*)&As[cur][kt8 * AKT_STRIDE + arow * 8 + 2 * lc];
                p2[i] = *(const float2*)&As[cur][kt8 * AKT_STRIDE + (arow + 8) * 8 + 2 * lc];
            }
            float bf[4][2];
            #pragma unroll
            for (int j = 0; j < 4; j++) {
                int bn = warpN + 8 * j + lr;
                bf[j][0] = Ws[cur][(k0 + lc) * WS_W + bn];
                bf[j][1] = Ws[cur][(k0 + lc + 4) * WS_W + bn];
            }
            #pragma unroll
            for (int i = 0; i < 2; i++)
                #pragma unroll
                for (int j = 0; j < 4; j++)
                    mma_tf32(acc[i][j], p1[i].x, p2[i].x, p1[i].y, p2[i].y,
                             bf[j][0], bf[j][1]);
        }
        if (kt + 1 < NT) {
            store_afrag(As[nxt], ar, akt, a0, a1);
            float* ws = &Ws[nxt][wr * WS_W + wc];
            ws[0] = tf32r(w4.x); ws[1] = tf32r(w4.y); ws[2] = tf32r(w4.z); ws[3] = tf32r(w4.w);
        }
        __syncthreads();
    }

    float2 bj[4];
    #pragma unroll
    for (int j = 0; j < 4; j++)
        bj[j] = *(const float2*)&bias[col0 + warpN + 8 * j + lc * 2];

    #pragma unroll
    for (int i = 0; i < 2; i++) {
        #pragma unroll
        for (int h = 0; h < 2; h++) {
            int m = row0 + warpM + 16 * i + lr + 8 * h;
            float g;
            if constexpr (EPI == EPI_GATEMUL) g = x1[m];
            #pragma unroll
            for (int j = 0; j < 4; j++) {
                int n = col0 + warpN + 8 * j + lc * 2;
                float v0 = acc[i][j][2 * h + 0] + bj[j].x;
                float v1 = acc[i][j][2 * h + 1] + bj[j].y;
                float2 o;
                if constexpr (EPI == EPI_GATEMUL) {
                    o.x = v0 * g;
                    o.y = v1 * g;
                } else if constexpr (EPI == EPI_GELU) {
                    o.x = 0.5f * v0 * (1.0f + erff(v0 * 0.70710678118654752f));
                    o.y = 0.5f * v1 * (1.0f + erff(v1 * 0.70710678118654752f));
                } else {
                    float2 xv = *(const float2*)&x1[(size_t)m * D_ + n];
                    o.x = xv.x + v0;
                    o.y = xv.y + v1;
                }
                *(float2*)&O1[(size_t)m * D_ + n] = o;
            }
        }
    }
}

// gate = sigmoid(x @ w_gate + b)
__global__ void k_gate(const float* __restrict__ x, const float* __restrict__ wg,
                       const float* __restrict__ bg, float* gate) {
    int w = threadIdx.x >> 5, lane = threadIdx.x & 31;
    int t = blockIdx.x * 8 + w;
    float acc = 0.f;
    #pragma unroll
    for (int i = 0; i < 8; i++) {
        int d = lane + i * 32;
        acc += x[(size_t)t * D_ + d] * wg[d];
    }
    #pragma unroll
    for (int o = 16; o > 0; o >>= 1) acc += __shfl_xor_sync(0xffffffffu, acc, o);
    if (lane == 0) gate[t] = 1.0f / (1.0f + expf(-(acc + bg[0])));
}

// parallel gate cumsum
__global__ void k_gscan(const float* __restrict__ gate, float* gcum) {
    __shared__ float wt[8];
    int b = blockIdx.x, tid = threadIdx.x, lane = tid & 31, warp = tid >> 5;
    int l0 = tid * 8;
    float v[8], t = 0.f;
    #pragma unroll
    for (int i = 0; i < 8; i++) { v[i] = gate[b * L_ + l0 + i]; t += v[i]; }
    float inc = wscan(t, lane);
    if (lane == 31) wt[warp] = inc;
    __syncthreads();
    float run = inc - t;
    for (int w = 0; w < warp; w++) run += wt[w];
    #pragma unroll
    for (int i = 0; i < 8; i++) {
        run += v[i];
        gcum[b * L_ + l0 + i] = fmaxf(1.0f, run);
    }
}

// context_avg 3-pass
__global__ void k_ctx1(const float* __restrict__ x, float* ctxs) {
    int b = blockIdx.x / NCH_, ch = blockIdx.x % NCH_, d = threadIdx.x;
    int m0 = b * L_ + ch * CH_;
    float acc = 0.f;
    #pragma unroll 8
    for (int l = 0; l < CH_; l++) acc += x[(size_t)(m0 + l) * D_ + d];
    ctxs[(b * NCH_ + ch) * D_ + d] = acc;
}
__global__ void k_ctx2(const float* __restrict__ ctxs, float* __restrict__ ctxs2) {
    int b = blockIdx.x, d = threadIdx.x;
    float v[NCH_];
    #pragma unroll
    for (int ch = 0; ch < NCH_; ch++) v[ch] = ctxs[(b * NCH_ + ch) * D_ + d];
    float run = 0.f;
    #pragma unroll
    for (int ch = 0; ch < NCH_; ch++) {
        ctxs2[(b * NCH_ + ch) * D_ + d] = run;
        run += v[ch];
    }
}
__global__ void k_ctx3(const float* __restrict__ x, const float* __restrict__ ctxs2, float* ctx) {
    int b = blockIdx.x / NCH_, ch = blockIdx.x % NCH_, d = threadIdx.x;
    float acc = ctxs2[(b * NCH_ + ch) * D_ + d];
    for (int l = 0; l < CH_; l++) {
        int gl = ch * CH_ + l;
        acc += x[(size_t)(b * L_ + gl) * D_ + d];
        ctx[(size_t)(b * L_ + gl) * D_ + d] = acc * (1.0f / (float)(gl + 1));
    }
}

// mem1 scan (parallel)
__global__ void k_m1scan(const float* __restrict__ v1, const float* __restrict__ posc,
                         const float* __restrict__ poss, const float* __restrict__ qc,
                         const float* __restrict__ qs, float* m1r) {
    __shared__ float wc_[8], ws_[8];
    int b = blockIdx.x / P_, p = blockIdx.x % P_;
    int tid = threadIdx.x, lane = tid & 31, warp = tid >> 5;
    int l0 = tid * 8;
    float c[8], s[8], tc = 0.f, ts = 0.f;
    #pragma unroll
    for (int i = 0; i < 8; i++) {
        int l = l0 + i;
        size_t m = (size_t)(b * L_ + l);
        float v = v1[m * P_ + p];
        c[i] = posc[l * P_ + p] * v;
        s[i] = poss[l * P_ + p] * v;
        tc += c[i];
        ts += s[i];
    }
    float ic = wscan(tc, lane), is_ = wscan(ts, lane);
    if (lane == 31) { wc_[warp] = ic; ws_[warp] = is_; }
    __syncthreads();
    float rc = ic - tc, rs = is_ - ts;
    for (int w = 0; w < warp; w++) { rc += wc_[w]; rs += ws_[w]; }
    #pragma unroll
    for (int i = 0; i < 8; i++) {
        rc += c[i];
        rs += s[i];
        size_t m = (size_t)(b * L_ + l0 + i);
        m1r[m * P_ + p] = (rc * qc[m * P_ + p] + rs * qs[m * P_ + p]) * INV_SQRT_P;
    }
}

// ---------------- kv pass1 on tensor cores, 3xTF32 (fp32-grade accuracy) ------
constexpr int KV1_SMEM = (2 * 64 * 72 + 2 * 16 * 264) * 4;  // 70656 B

__launch_bounds__(256)
__global__ void k_kv1(const float* __restrict__ cc, const float* __restrict__ cs,
                      const float* __restrict__ gv, float* __restrict__ A) {
    extern __shared__ float sm[];
    float* sCH = sm;                 // 64 x 72  (cc|cs hi, [l][row])
    float* sCL = sm + 4608;          // lo
    float* sGH = sm + 9216;          // 16 x 264 (gv stage hi, [l][d])
    float* sGL = sm + 9216 + 4224;   // lo
    int b = blockIdx.x / NCH_, ch = blockIdx.x % NCH_;
    int m0 = b * L_ + ch * CH_;
    int tid = threadIdx.x, lane = tid & 31, warp = tid >> 5;
    int lr = lane >> 2, lc = lane & 3;
    int wm = (warp >> 2) * 32, wn = (warp & 3) * 64;

    for (int i = tid; i < 64 * 64; i += 256) {
        int l = i >> 6, row = i & 63;
        float v = (row < 32) ? cc[(size_t)(m0 + l) * P_ + row]
                             : cs[(size_t)(m0 + l) * P_ + row - 32];
        float hi = tf32r(v);
        sCH[l * 72 + row] = hi;
        sCL[l * 72 + row] = tf32r(v - hi);
    }

    float acc[2][8][4];
    #pragma unroll
    for (int i = 0; i < 2; i++)
        #pragma unroll
        for (int j = 0; j < 8; j++)
            #pragma unroll
            for (int q = 0; q < 4; q++) acc[i][j][q] = 0.f;

    int r = tid >> 4, c0 = (tid & 15) * 16;
    for (int st = 0; st < 4; st++) {
        #pragma unroll
        for (int q = 0; q < 4; q++) {
            float4 v4 = *(const float4*)&gv[(size_t)(m0 + st * 16 + r) * D_ + c0 + q * 4];
            float h0 = tf32r(v4.x), h1 = tf32r(v4.y), h2 = tf32r(v4.z), h3 = tf32r(v4.w);
            float* gh = &sGH[r * 264 + c0 + q * 4];
            float* gl = &sGL[r * 264 + c0 + q * 4];
            gh[0] = h0; gh[1] = h1; gh[2] = h2; gh[3] = h3;
            gl[0] = tf32r(v4.x - h0); gl[1] = tf32r(v4.y - h1);
            gl[2] = tf32r(v4.z - h2); gl[3] = tf32r(v4.w - h3);
        }
        __syncthreads();
        #pragma unroll
        for (int k0 = 0; k0 < 16; k0 += 8) {
            int kk = st * 16 + k0;
            float ah[2][4], al[2][4];
            #pragma unroll
            for (int i = 0; i < 2; i++) {
                int row = wm + 16 * i + lr;
                ah[i][0] = sCH[(kk + lc) * 72 + row];
                ah[i][1] = sCH[(kk + lc) * 72 + row + 8];
                ah[i][2] = sCH[(kk + lc + 4) * 72 + row];
                ah[i][3] = sCH[(kk + lc + 4) * 72 + row + 8];
                al[i][0] = sCL[(kk + lc) * 72 + row];
                al[i][1] = sCL[(kk + lc) * 72 + row + 8];
                al[i][2] = sCL[(kk + lc + 4) * 72 + row];
                al[i][3] = sCL[(kk + lc + 4) * 72 + row + 8];
            }
            #pragma unroll
            for (int j = 0; j < 8; j++) {
                int nn = wn + 8 * j + lr;
                float bh0 = sGH[(k0 + lc) * 264 + nn];
                float bh1 = sGH[(k0 + lc + 4) * 264 + nn];
                float bl0 = sGL[(k0 + lc) * 264 + nn];
                float bl1 = sGL[(k0 + lc + 4) * 264 + nn];
                #pragma unroll
                for (int i = 0; i < 2; i++) {
                    mma_tf32(acc[i][j], ah[i][0], ah[i][1], ah[i][2], ah[i][3], bh0, bh1);
                    mma_tf32(acc[i][j], ah[i][0], ah[i][1], ah[i][2], ah[i][3], bl0, bl1);
                    mma_tf32(acc[i][j], al[i][0], al[i][1], al[i][2], al[i][3], bh0, bh1);
                }
            }
        }
        __syncthreads();
    }

    size_t base = (size_t)(b * NCH_ + ch) * 2 * P_ * D_;
    #pragma unroll
    for (int i = 0; i < 2; i++)
        #pragma unroll
        for (int h = 0; h < 2; h++) {
            int row = wm + 16 * i + lr + 8 * h;
            #pragma unroll
            for (int j = 0; j < 8; j++) {
                int col = wn + 8 * j + 2 * lc;
                float2 o;
                o.x = acc[i][j][2 * h + 0];
                o.y = acc[i][j][2 * h + 1];
                *(float2*)&A[base + (size_t)row * D_ + col] = o;
            }
        }
}

// kv pass2: exclusive prefix of A over chunks (batched loads)
__global__ void k_kv2(const float* __restrict__ A, float* __restrict__ Apre) {
    int idx = blockIdx.x * 256 + threadIdx.x;
    int e = idx % (2 * P_ * D_), b = idx / (2 * P_ * D_);
    float v[NCH_];
    #pragma unroll
    for (int ch = 0; ch < NCH_; ch++)
        v[ch] = A[(size_t)(b * NCH_ + ch) * 2 * P_ * D_ + e];
    float run = 0.f;
    #pragma unroll
    for (int ch = 0; ch < NCH_; ch++) {
        Apre[(size_t)(b * NCH_ + ch) * 2 * P_ * D_ + e] = run;
        run += v[ch];
    }
}

// ---------------- kv pass3: fully tensorized + fused LN ----------------
constexpr int SK_  = 0;        // 64 x 68  (kc|ks tf32)
constexpr int SC_  = 4352;     // 64 x 68  (cc|cs tf32)
constexpr int SAC_ = 8704;     // 64 x 164 (A operand: scores|K2|m1r)
constexpr int SBT_ = 0;        // 16 x 260 (B staging, reuses SK after phase1)
constexpr int SOUT_ = 0;       // 64 x 260 (result, reuses all after phase2)
constexpr int KV3_SMEM = 19200 * 4;   // 76800 bytes

__launch_bounds__(256)
__global__ void k_kv3(const float* __restrict__ kc, const float* __restrict__ ks,
                      const float* __restrict__ cc, const float* __restrict__ cs,
                      const float* __restrict__ gv, const float* __restrict__ Apre,
                      const float* __restrict__ m1r, const float* __restrict__ gcum,
                      const float* __restrict__ w_mo, const float* __restrict__ b_mo,
                      const float* __restrict__ lng, const float* __restrict__ lnb,
                      float* __restrict__ y) {
    extern __shared__ float sm[];
    __shared__ float s_scl[64];
    int b = blockIdx.x / NCH_, ch = blockIdx.x % NCH_;
    int m0 = b * L_ + ch * CH_;
    int tid = threadIdx.x, lane = tid & 31, warp = tid >> 5;
    int lr = lane >> 2, lc = lane & 3;

    for (int i = tid; i < CH_ * P_; i += 256) {
        int l = i >> 5, p = i & 31;
        size_t gi = (size_t)(m0 + l) * P_ + p;
        sm[SK_ + l * 68 + p]      = tf32r(kc[gi]);
        sm[SK_ + l * 68 + 32 + p] = tf32r(ks[gi]);
        sm[SC_ + l * 68 + p]      = tf32r(cc[gi]);
        sm[SC_ + l * 68 + 32 + p] = tf32r(cs[gi]);
        sm[SAC_ + l * 164 + 128 + p] = tf32r(m1r[gi]);
    }
    if (tid < 64) s_scl[tid] = rsqrtf(gcum[m0 + tid]) * INV_SQRT_P;
    __syncthreads();

    // phase 1: scores[64,64] = [kc|ks] @ [cc|cs]^T (K=64), warps 2x4 (32x16)
    {
        int wm = (warp >> 2) * 32, wn = (warp & 3) * 16;
        float a2[2][2][4];
        #pragma unroll
        for (int i = 0; i < 2; i++)
            #pragma unroll
            for (int j = 0; j < 2; j++)
                #pragma unroll
                for (int q = 0; q < 4; q++) a2[i][j][q] = 0.f;
        #pragma unroll
        for (int kk = 0; kk < 8; kk++) {
            int k0 = kk * 8;
            float af[2][4];
            #pragma unroll
            for (int i = 0; i < 2; i++) {
                int row = wm + 16 * i + lr;
                af[i][0] = sm[SK_ + row * 68 + k0 + lc];
                af[i][1] = sm[SK_ + (row + 8) * 68 + k0 + lc];
                af[i][2] = sm[SK_ + row * 68 + k0 + lc + 4];
                af[i][3] = sm[SK_ + (row + 8) * 68 + k0 + lc + 4];
            }
            #pragma unroll
            for (int j = 0; j < 2; j++) {
                int nn = wn + 8 * j + lr;
                float b0 = sm[SC_ + nn * 68 + k0 + lc];
                float b1 = sm[SC_ + nn * 68 + k0 + lc + 4];
                #pragma unroll
                for (int i = 0; i < 2; i++)
                    mma_tf32(a2[i][j], af[i][0], af[i][1], af[i][2], af[i][3], b0, b1);
            }
        }
        #pragma unroll
        for (int i = 0; i < 2; i++)
            #pragma unroll
            for (int j = 0; j < 2; j++)
                #pragma unroll
                for (int h = 0; h < 2; h++) {
                    int row = wm + 16 * i + lr + 8 * h;
                    float sl = s_scl[row];
                    int col = wn + 8 * j + 2 * lc;
                    sm[SAC_ + row * 164 + col] =
                        (col <= row) ? tf32r(a2[i][j][2 * h] * sl) : 0.f;
                    sm[SAC_ + row * 164 + col + 1] =
                        (col + 1 <= row) ? tf32r(a2[i][j][2 * h + 1] * sl) : 0.f;
                }
    }
    // K2 columns: s_ac[l][64+c] = scl[l] * [kc|ks][l][c]
    #pragma unroll
    for (int t = 0; t < 16; t++) {
        int idx = tid * 16 + t;
        int l = idx >> 6, c = idx & 63;
        sm[SAC_ + l * 164 + 64 + c] = tf32r(s_scl[l] * sm[SK_ + l * 68 + c]);
    }
    __syncthreads();

    // phase 2: [64,160] @ [160,256], warps 2x4 (32x64)
    float acc[2][8][4];
    #pragma unroll
    for (int i = 0; i < 2; i++)
        #pragma unroll
        for (int j = 0; j < 8; j++)
            #pragma unroll
            for (int q = 0; q < 4; q++) acc[i][j][q] = 0.f;
    int wm2 = (warp >> 2) * 32, wn2 = (warp & 3) * 64;
    size_t abase = (size_t)(b * NCH_ + ch) * 2 * P_ * D_;
    for (int st = 0; st < 10; st++) {
        int r = tid >> 4, c0 = (tid & 15) * 16;
        int gr = st * 16 + r;
        const float* src;
        if (gr < 64)       src = &gv[(size_t)(m0 + gr) * D_];
        else if (gr < 128) src = &Apre[abase + (size_t)(gr - 64) * D_];
        else               src = &w_mo[(size_t)(gr - 128) * D_];
        #pragma unroll
        for (int q = 0; q < 4; q++) {
            float4 v = *(const float4*)&src[c0 + q * 4];
            float* dst = &sm[SBT_ + r * 260 + c0 + q * 4];
            dst[0] = tf32r(v.x); dst[1] = tf32r(v.y);
            dst[2] = tf32r(v.z); dst[3] = tf32r(v.w);
        }
        __syncthreads();
        #pragma unroll
        for (int k0 = 0; k0 < 16; k0 += 8) {
            float af[2][4];
            #pragma unroll
            for (int i = 0; i < 2; i++) {
                int row = wm2 + 16 * i + lr;
                af[i][0] = sm[SAC_ + row * 164 + st * 16 + k0 + lc];
                af[i][1] = sm[SAC_ + (row + 8) * 164 + st * 16 + k0 + lc];
                af[i][2] = sm[SAC_ + row * 164 + st * 16 + k0 + lc + 4];
                af[i][3] = sm[SAC_ + (row + 8) * 164 + st * 16 + k0 + lc + 4];
            }
            #pragma unroll
            for (int j = 0; j < 8; j++) {
                int nn = wn2 + 8 * j + lr;
                float b0 = sm[SBT_ + (k0 + lc) * 260 + nn];
                float b1 = sm[SBT_ + (k0 + lc + 4) * 260 + nn];
                #pragma unroll
                for (int i = 0; i < 2; i++)
                    mma_tf32(acc[i][j], af[i][0], af[i][1], af[i][2], af[i][3], b0, b1);
            }
        }
        __syncthreads();
    }

    // stash result (+bias) in smem for the LN pass
    #pragma unroll
    for (int j = 0; j < 8; j++) {
        int col = wn2 + 8 * j + 2 * lc;
        float2 bb = *(const float2*)&b_mo[col];
        #pragma unroll
        for (int i = 0; i < 2; i++) {
            int row = wm2 + 16 * i + lr;
            sm[SOUT_ + row * 260 + col]           = acc[i][j][0] + bb.x;
            sm[SOUT_ + row * 260 + col + 1]       = acc[i][j][1] + bb.y;
            sm[SOUT_ + (row + 8) * 260 + col]     = acc[i][j][2] + bb.x;
            sm[SOUT_ + (row + 8) * 260 + col + 1] = acc[i][j][3] + bb.y;
        }
    }
    __syncthreads();

    // LayerNorm: warp w handles rows w*8 .. w*8+7
    for (int rr = 0; rr < 8; rr++) {
        int r = warp * 8 + rr;
        float v[8], s = 0.f;
        #pragma unroll
        for (int q = 0; q < 8; q++) {
            v[q] = sm[SOUT_ + r * 260 + lane + 32 * q];
            s += v[q];
        }
        #pragma unroll
        for (int o = 16; o > 0; o >>= 1) s += __shfl_xor_sync(0xffffffffu, s, o);
        float mu = s * (1.0f / 256.0f);
        float qv = 0.f;
        #pragma unroll
        for (int q = 0; q < 8; q++) { float d = v[q] - mu; qv += d * d; }
        #pragma unroll
        for (int o = 16; o > 0; o >>= 1) qv += __shfl_xor_sync(0xffffffffu, qv, o);
        float inv = rsqrtf(qv * (1.0f / 256.0f) + 1e-5f);
        int m = m0 + r;
        #pragma unroll
        for (int q = 0; q < 8; q++) {
            int n = lane + 32 * q;
            y[(size_t)m * D_ + n] = (v[q] - mu) * inv * lng[n] + lnb[n];
        }
    }
}

extern "C" void kernel_launch(void* const* d_in, const int* in_sizes, int n_in,
                              void* d_out, int out_size) {
    const float* x       = (const float*)d_in[0];
    const float* pp      = (const float*)d_in[1];
    const float* w_mem1v = (const float*)d_in[2];
    const float* b_mem1v = (const float*)d_in[3];
    const float* w_mem1o = (const float*)d_in[4];
    const float* b_mem1o = (const float*)d_in[5];
    const float* w_off   = (const float*)d_in[6];
    const float* b_off   = (const float*)d_in[7];
    const float* w_key   = (const float*)d_in[8];
    const float* b_key   = (const float*)d_in[9];
    const float* w_val   = (const float*)d_in[10];
    const float* b_val   = (const float*)d_in[11];
    const float* w_sk1   = (const float*)d_in[12];
    const float* b_sk1   = (const float*)d_in[13];
    const float* w_sk2   = (const float*)d_in[14];
    const float* b_sk2   = (const float*)d_in[15];
    const float* w_gate  = (const float*)d_in[16];
    const float* b_gate  = (const float*)d_in[17];
    const float* ln_g    = (const float*)d_in[18];
    const float* ln_b    = (const float*)d_in[19];
    const float* w_out   = (const float*)d_in[20];
    const float* b_out   = (const float*)d_in[21];
    float* out = (float*)d_out;

    float* base = nullptr;
    cudaGetSymbolAddress((void**)&base, g_buf);
    float* posc = base + O_POSC; float* poss = base + O_POSS; float* posw = base + O_POSW;
    float* v1   = base + O_V1;   float* qc   = base + O_QC;   float* qs   = base + O_QS;
    float* kc   = base + O_KC;   float* ks   = base + O_KS;   float* ccp  = base + O_CC;
    float* csp  = base + O_CS;   float* m1r  = base + O_M1R;  float* gate = base + O_GATE;
    float* gcum = base + O_GCUM; float* gv   = base + O_GV;   float* ctx  = base + O_CTX;
    float* h    = base + O_H;    float* y    = base + O_Y;
    float* ctxs = base + O_CTXS; float* Am   = base + O_A;    float* Apre = base + O_APRE;
    float* ctxs2 = base + O_CTXS2;

    cudaFuncSetAttribute(k_kv3, cudaFuncAttributeMaxDynamicSharedMemorySize, KV3_SMEM);
    cudaFuncSetAttribute(k_kv1, cudaFuncAttributeMaxDynamicSharedMemorySize, KV1_SMEM);

    dim3 gP(M_ / 128, 3);
    dim3 gBig(M_ / 128, 4);

    // order chosen so the profiled launch (index 3) is the big sk1 GEMM
    k_ctx1<<<B_ * NCH_, 256>>>(x, ctxs);
    k_ctx2<<<B_, 256>>>(ctxs, ctxs2);
    k_ctx3<<<B_ * NCH_, 256>>>(x, ctxs2, ctx);
    k_bgemm<512, EPI_GELU, true><<<gBig, 256>>>(x, ctx, w_sk1, b_sk1, h, nullptr);
    k_pos<<<(L_ * P_ + 255) / 256, 256>>>(pp, w_off, b_off, posc, poss, posw);
    k_pgemm<<<gP, 256>>>(x, w_mem1v, b_mem1v, w_off, w_key, b_key, posw, posc, poss,
                         v1, qc, qs, kc, ks, -1);
    k_gate<<<M_ / 8, 256>>>(x, w_gate, b_gate, gate);
    k_gscan<<<B_, 256>>>(gate, gcum);
    k_bgemm<256, EPI_GATEMUL, false><<<gBig, 256>>>(x, nullptr, w_val, b_val, gv, gate);
    k_pgemm<<<dim3(M_ / 128, 1), 256>>>(h, nullptr, nullptr, nullptr, w_sk2, b_sk2,
                                        nullptr, nullptr, nullptr,
                                        nullptr, nullptr, nullptr, ccp, csp, 2);
    k_m1scan<<<B_ * P_, 256>>>(v1, posc, poss, qc, qs, m1r);
    k_kv1<<<B_ * NCH_, 256, KV1_SMEM>>>(ccp, csp, gv, Am);
    k_kv2<<<B_ * 2 * P_ * D_ / 256, 256>>>(Am, Apre);
    k_kv3<<<B_ * NCH_, 256, KV3_SMEM>>>(kc, ks, ccp, csp, gv, Apre, m1r, gcum,
                                        w_mem1o, b_mem1o, ln_g, ln_b, y);
    k_bgemm<256, EPI_RESID, false><<<gBig, 256>>>(y, nullptr, w_out, b_out, out, x);
}